// round 10
// baseline (speedup 1.0000x reference)
#include <cuda_runtime.h>
#include <cstdint>

// MeanCellExtrator v8: occupancy experiment — tensor-split CTAs.
//   - grid (92, 4 images, 2 tensors) = 736 CTAs, 256 thr, 5 CTAs/SM (39 KB smem)
//     -> 40 warps/SM (occ 62.5%, was 36.5%).
//   - CTA handles ONE tensor (pred or targ = blockIdx.z); warp w owns
//     channels {2w, 2w+1} -> race-free across warps.
//   - dup labels in warp serialized by rank rounds (v7 scheme): rank =
//     popc(match & lt), mx = redux.max; round r lanes RMW float2 acc.
//   - label 0 accumulates into never-read slot 0.
//   - labels staged per-CTA in smem (controls v2's label-traffic confound).
//   - no prefetch (v6 proved MLP irrelevant; saves regs under forced 51).
//   - merge via red.global.add.v4 into __device__ scratch; counts merged by
//     pred-CTAs only; last CTA finalizes into d_out and re-zeros scratch.

#define FULLMASK 0xffffffffu

constexpr int C       = 16;
constexpr int HW      = 1 << 20;
constexpr int NLAB    = 512;
constexpr int STRIPS  = 92;              // 92*4*2 = 736 CTAs ~= 5/SM
constexpr int NG      = HW / 128;        // 8192 groups of 128 px per image
constexpr int PROW    = 1026;            // float2 pair-row stride (floats)
constexpr int ACC_F   = 8 * PROW + 513;  // 8 pair rows + cnt = 8721
constexpr int ACC_PAD = (ACC_F + 3) & ~3;        // 8724, slab 16B-aligned
constexpr int STAGE_G = 8;
constexpr int LAB_I   = STAGE_G * 128;   // 1024 staged labels
constexpr int SMEM_F  = ACC_PAD + LAB_I; // 9748 floats = 38992 B

__device__ __align__(16) float g_acc[67584];
__device__ unsigned g_done = 0;

__device__ __forceinline__ void red4(float* p, float a, float b, float c, float d) {
    asm volatile("red.global.add.v4.f32 [%0], {%1,%2,%3,%4};"
                 :: "l"(p), "f"(a), "f"(b), "f"(c), "f"(d) : "memory");
}

__global__ __launch_bounds__(256, 5)
void fused_kernel(const float* __restrict__ pred,
                  const float* __restrict__ targ,
                  const int*   __restrict__ nuc,
                  float* __restrict__ out, int nCTA)
{
    extern __shared__ float sm[];
    float* cnt  = sm + 8 * PROW;
    int*   slab = (int*)(sm + ACC_PAD);
    __shared__ int lastFlag;

    const int tid  = threadIdx.x;
    const int warp = tid >> 5;
    const int lane = tid & 31;
    const int b    = blockIdx.y;
    const int t    = blockIdx.z;     // 0 = pred, 1 = targ
    const int s    = blockIdx.x;

    // ---- zero accumulators ----
    {
        float4 z = make_float4(0.f, 0.f, 0.f, 0.f);
        float4* p4 = reinterpret_cast<float4*>(sm);
        for (int i = tid; i < (ACC_PAD >> 2); i += 256) p4[i] = z;
    }

    const float* planeBase = (t ? targ : pred)
                             + (size_t)(b * C + warp * 2) * HW;
    const int* lab = nuc + (size_t)b * HW;
    float2* pair = reinterpret_cast<float2*>(sm + warp * PROW);
    const bool doCnt = (warp == 0);

    const int g0 = (s * NG) / STRIPS;
    const int g1 = ((s + 1) * NG) / STRIPS;

    for (int gs = g0; gs < g1; gs += STAGE_G) {
        const int ge = min(gs + STAGE_G, g1);
        __syncthreads();   // WAR on slab (and first-iter acc-zero ordering)
        {
            const int n4 = ((ge - gs) * 128) >> 2;
            int4* dst = (int4*)slab;
            const int4* src = (const int4*)(lab + gs * 128);
            for (int i = tid; i < n4; i += 256) dst[i] = __ldg(src + i);
        }
        __syncthreads();

        for (int g = gs; g < ge; ++g) {
            const int baseG = (g << 7) + (lane << 2);

            float4 V0 = __ldg((const float4*)(planeBase + baseG));
            float4 V1 = __ldg((const float4*)(planeBase + HW + baseG));
            int4 L = *(const int4*)(slab + ((g - gs) << 7) + (lane << 2));

            const int   lv[4] = {L.x, L.y, L.z, L.w};
            const float c0[4] = {V0.x, V0.y, V0.z, V0.w};
            const float c1[4] = {V1.x, V1.y, V1.z, V1.w};

            #pragma unroll
            for (int j = 0; j < 4; ++j) {
                const int   label = lv[j];
                const float v0 = c0[j], v1 = c1[j];

                const unsigned grp  = __match_any_sync(FULLMASK, label);
                const int      rank = __popc(grp & ((1u << lane) - 1u));
                const int      mx   = __reduce_max_sync(FULLMASK, rank);

                if (rank == 0) {
                    float2 x = pair[label]; x.x += v0; x.y += v1; pair[label] = x;
                    if (doCnt) cnt[label] += (float)__popc(grp);
                }
                for (int r = 1; r <= mx; ++r) {
                    if (rank == r) {
                        float2 x = pair[label]; x.x += v0; x.y += v1; pair[label] = x;
                    }
                }
            }
        }
    }
    __syncthreads();

    // ---- merge partials into global scratch ----
    {
        float* base = g_acc + (t ? 32768 : 0);
        for (int r = tid; r < NLAB; r += 256) {
            const int   L = r + 1;
            const float c = cnt[L];
            if (c != 0.f) {
                const int gi = b * NLAB + r;
                float* po = base + (size_t)gi * C;
                #pragma unroll
                for (int k = 0; k < 16; k += 4)
                    red4(po + k,
                         sm[(k >> 1) * PROW + 2 * L],
                         sm[(k >> 1) * PROW + 2 * L + 1],
                         sm[((k >> 1) | 1) * PROW + 2 * L],
                         sm[((k >> 1) | 1) * PROW + 2 * L + 1]);
                if (t == 0) atomicAdd(g_acc + 65536 + gi, c);
            }
        }
    }
    __threadfence();
    __syncthreads();
    if (tid == 0) lastFlag = (atomicAdd(&g_done, 1u) == (unsigned)(nCTA - 1));
    __syncthreads();

    // ---- last CTA: finalize into d_out, re-zero scratch ----
    if (lastFlag) {
        __threadfence();
        const float4 z = make_float4(0.f, 0.f, 0.f, 0.f);
        for (int i = tid; i < 4 * NLAB; i += 256) {
            const float c = g_acc[65536 + i];
            const float inv = 1.0f / fmaxf(c, 1.0f);
            float4* gp = reinterpret_cast<float4*>(g_acc + (size_t)i * C);
            float4* gt = reinterpret_cast<float4*>(g_acc + 32768 + (size_t)i * C);
            float4* op = reinterpret_cast<float4*>(out + (size_t)i * C);
            float4* ot = reinterpret_cast<float4*>(out + 32768 + (size_t)i * C);
            #pragma unroll
            for (int q = 0; q < 4; ++q) {
                float4 vp = gp[q], vt = gt[q];
                vp.x *= inv; vp.y *= inv; vp.z *= inv; vp.w *= inv;
                vt.x *= inv; vt.y *= inv; vt.z *= inv; vt.w *= inv;
                op[q] = vp; ot[q] = vt;
                gp[q] = z;  gt[q] = z;
            }
            out[65536 + i]   = (c > 0.f) ? (float)((i & (NLAB - 1)) + 1) : 0.f;
            g_acc[65536 + i] = 0.f;
        }
        __syncthreads();
        if (tid == 0) g_done = 0u;
    }
}

extern "C" void kernel_launch(void* const* d_in, const int* in_sizes, int n_in,
                              void* d_out, int out_size)
{
    const float* pred = (const float*)d_in[0];
    const float* targ = (const float*)d_in[1];
    const int*   nuc  = (const int*)d_in[2];
    float* out = (float*)d_out;

    const int B = in_sizes[2] / HW;   // 4

    const int smemB = SMEM_F * (int)sizeof(float);
    cudaFuncSetAttribute(fused_kernel,
                         cudaFuncAttributeMaxDynamicSharedMemorySize, smemB);

    dim3 grid(STRIPS, B, 2);
    fused_kernel<<<grid, 256, smemB>>>(pred, targ, nuc, out, STRIPS * B * 2);
}

// round 11
// speedup vs baseline: 2.5500x; 2.5500x over previous
#include <cuda_runtime.h>
#include <cstdint>

// MeanCellExtrator v9: match-once-share-8x.
//   - grid (111,4) = 444 CTAs, 256 thr, 3 CTAs/SM (71.8 KB smem).
//   - STAGE: warp w stages group gs+w: loads 128 labels in the consumption
//     layout, computes match/rank/mx/popc ONCE per j-step, stores packed
//     word  label | rank<<10 | mx<<15 | popc<<20  to slab.
//   - CONSUME: all 8 warps, warp owns 4 channels [4w,4w+4) (pred for w<4,
//     targ for w>=4) as two float2 rows. Zero warp-collectives: unpack +
//     rank-round predicated float2 RMW (program order serializes dups;
//     mx is warp-uniform so the round loop stays converged).
//   - label 0 accumulates into never-read slot 0.
//   - merge via red.global.add.v4 into __device__ scratch; last CTA
//     finalizes into d_out and re-zeros scratch (deterministic replays).

#define FULLMASK 0xffffffffu

constexpr int C       = 16;
constexpr int HW      = 1 << 20;
constexpr int NLAB    = 512;
constexpr int STRIPS  = 111;             // 444 CTAs = 3/SM
constexpr int NG      = HW / 128;        // 8192 groups of 128 px per image
constexpr int PROW    = 1026;            // float2 pair-row stride (floats)
constexpr int ACC_F   = 16 * PROW + 513; // 16 pair rows + cnt = 16929
constexpr int ACC_PAD = (ACC_F + 3) & ~3;        // 16932, slab 16B-aligned
constexpr int STAGE_G = 8;               // one group per warp
constexpr int LAB_I   = STAGE_G * 128;   // 1024 packed words
constexpr int SMEM_F  = ACC_PAD + LAB_I; // 17956 floats = 71824 B

__device__ __align__(16) float g_acc[67584];
__device__ unsigned g_done = 0;

__device__ __forceinline__ void red4(float* p, float a, float b, float c, float d) {
    asm volatile("red.global.add.v4.f32 [%0], {%1,%2,%3,%4};"
                 :: "l"(p), "f"(a), "f"(b), "f"(c), "f"(d) : "memory");
}

__global__ __launch_bounds__(256, 3)
void fused_kernel(const float* __restrict__ pred,
                  const float* __restrict__ targ,
                  const int*   __restrict__ nuc,
                  float* __restrict__ out, int nCTA)
{
    extern __shared__ float sm[];
    float* cnt  = sm + 16 * PROW;
    int*   slab = (int*)(sm + ACC_PAD);
    __shared__ int lastFlag;

    const int tid  = threadIdx.x;
    const int warp = tid >> 5;
    const int lane = tid & 31;
    const int b    = blockIdx.y;
    const int s    = blockIdx.x;

    // ---- zero accumulators ----
    {
        float4 z = make_float4(0.f, 0.f, 0.f, 0.f);
        float4* p4 = reinterpret_cast<float4*>(sm);
        for (int i = tid; i < (ACC_PAD >> 2); i += 256) p4[i] = z;
    }

    const float* planeBase = ((warp >= 4) ? targ : pred)
                             + (size_t)(b * C + (warp & 3) * 4) * HW;
    const int* lab = nuc + (size_t)b * HW;
    float2* pairA = reinterpret_cast<float2*>(sm + (2 * warp)     * PROW);
    float2* pairB = reinterpret_cast<float2*>(sm + (2 * warp + 1) * PROW);
    const bool doCnt = (warp == 0);

    const int g0 = (s * NG) / STRIPS;
    const int g1 = ((s + 1) * NG) / STRIPS;

    for (int gs = g0; gs < g1; gs += STAGE_G) {
        const int ge = min(gs + STAGE_G, g1);
        __syncthreads();   // WAR on slab (and first-iter acc-zero ordering)

        // ---- STAGE: warp w preprocesses group gs+w (match ONCE) ----
        if (warp < ge - gs) {
            const int g = gs + warp;
            int4 L = __ldg((const int4*)(lab + (g << 7) + (lane << 2)));
            int lv[4] = {L.x, L.y, L.z, L.w};
            #pragma unroll
            for (int j = 0; j < 4; ++j) {
                const int label = lv[j];
                const unsigned grp  = __match_any_sync(FULLMASK, label);
                const int      rank = __popc(grp & ((1u << lane) - 1u));
                const int      mx   = __reduce_max_sync(FULLMASK, rank);
                const int      pc   = __popc(grp);
                lv[j] = label | (rank << 10) | (mx << 15) | (pc << 20);
            }
            *(int4*)(slab + (warp << 7) + (lane << 2)) =
                make_int4(lv[0], lv[1], lv[2], lv[3]);
        }
        __syncthreads();

        // ---- CONSUME: all warps, no warp-collectives ----
        for (int g = gs; g < ge; ++g) {
            const int baseG = (g << 7) + (lane << 2);
            float4 V0 = __ldg((const float4*)(planeBase + baseG));
            float4 V1 = __ldg((const float4*)(planeBase + HW + baseG));
            float4 V2 = __ldg((const float4*)(planeBase + 2 * (size_t)HW + baseG));
            float4 V3 = __ldg((const float4*)(planeBase + 3 * (size_t)HW + baseG));
            int4 P = *(const int4*)(slab + ((g - gs) << 7) + (lane << 2));

            const int   pv[4] = {P.x, P.y, P.z, P.w};
            const float c0[4] = {V0.x, V0.y, V0.z, V0.w};
            const float c1[4] = {V1.x, V1.y, V1.z, V1.w};
            const float c2[4] = {V2.x, V2.y, V2.z, V2.w};
            const float c3[4] = {V3.x, V3.y, V3.z, V3.w};

            #pragma unroll
            for (int j = 0; j < 4; ++j) {
                const int p     = pv[j];
                const int label = p & 1023;
                const int rank  = (p >> 10) & 31;
                const int mx    = (p >> 15) & 31;   // warp-uniform

                if (rank == 0) {
                    float2 x = pairA[label]; x.x += c0[j]; x.y += c1[j]; pairA[label] = x;
                    float2 y = pairB[label]; y.x += c2[j]; y.y += c3[j]; pairB[label] = y;
                    if (doCnt) cnt[label] += (float)((p >> 20) & 63);
                }
                for (int r = 1; r <= mx; ++r) {      // rare (mx>=1 ~62%)
                    if (rank == r) {
                        float2 x = pairA[label]; x.x += c0[j]; x.y += c1[j]; pairA[label] = x;
                        float2 y = pairB[label]; y.x += c2[j]; y.y += c3[j]; pairB[label] = y;
                    }
                }
            }
        }
    }
    __syncthreads();

    // ---- merge partials into global scratch ----
    for (int r = tid; r < NLAB; r += 256) {
        const int   L = r + 1;
        const float c = cnt[L];
        if (c != 0.f) {
            const int gi = b * NLAB + r;
            float* po = g_acc + (size_t)gi * C;
            float* to = g_acc + 32768 + (size_t)gi * C;
            #pragma unroll
            for (int k = 0; k < 16; k += 4)    // pred channels k..k+3
                red4(po + k,
                     sm[(k >> 1) * PROW + 2 * L],     sm[(k >> 1) * PROW + 2 * L + 1],
                     sm[(k >> 1 | 1) * PROW + 2 * L], sm[(k >> 1 | 1) * PROW + 2 * L + 1]);
            #pragma unroll
            for (int k = 0; k < 16; k += 4)    // targ channels
                red4(to + k,
                     sm[(8 + (k >> 1)) * PROW + 2 * L],     sm[(8 + (k >> 1)) * PROW + 2 * L + 1],
                     sm[(8 + (k >> 1 | 1)) * PROW + 2 * L], sm[(8 + (k >> 1 | 1)) * PROW + 2 * L + 1]);
            atomicAdd(g_acc + 65536 + gi, c);
        }
    }
    __threadfence();
    __syncthreads();
    if (tid == 0) lastFlag = (atomicAdd(&g_done, 1u) == (unsigned)(nCTA - 1));
    __syncthreads();

    // ---- last CTA: finalize into d_out, re-zero scratch ----
    if (lastFlag) {
        __threadfence();
        const float4 z = make_float4(0.f, 0.f, 0.f, 0.f);
        for (int i = tid; i < 4 * NLAB; i += 256) {
            const float c = g_acc[65536 + i];
            const float inv = 1.0f / fmaxf(c, 1.0f);
            float4* gp = reinterpret_cast<float4*>(g_acc + (size_t)i * C);
            float4* gt = reinterpret_cast<float4*>(g_acc + 32768 + (size_t)i * C);
            float4* op = reinterpret_cast<float4*>(out + (size_t)i * C);
            float4* ot = reinterpret_cast<float4*>(out + 32768 + (size_t)i * C);
            #pragma unroll
            for (int q = 0; q < 4; ++q) {
                float4 vp = gp[q], vt = gt[q];
                vp.x *= inv; vp.y *= inv; vp.z *= inv; vp.w *= inv;
                vt.x *= inv; vt.y *= inv; vt.z *= inv; vt.w *= inv;
                op[q] = vp; ot[q] = vt;
                gp[q] = z;  gt[q] = z;
            }
            out[65536 + i]   = (c > 0.f) ? (float)((i & (NLAB - 1)) + 1) : 0.f;
            g_acc[65536 + i] = 0.f;
        }
        __syncthreads();
        if (tid == 0) g_done = 0u;
    }
}

extern "C" void kernel_launch(void* const* d_in, const int* in_sizes, int n_in,
                              void* d_out, int out_size)
{
    const float* pred = (const float*)d_in[0];
    const float* targ = (const float*)d_in[1];
    const int*   nuc  = (const int*)d_in[2];
    float* out = (float*)d_out;

    const int B = in_sizes[2] / HW;   // 4

    const int smemB = SMEM_F * (int)sizeof(float);
    cudaFuncSetAttribute(fused_kernel,
                         cudaFuncAttributeMaxDynamicSharedMemorySize, smemB);

    dim3 grid(STRIPS, B);
    fused_kernel<<<grid, 256, smemB>>>(pred, targ, nuc, out, STRIPS * B);
}

// round 13
// speedup vs baseline: 2.7801x; 1.0902x over previous
#include <cuda_runtime.h>
#include <cstdint>

// MeanCellExtrator v10: v9 (match-once-share-8x) + float4 single-access RMW.
//   - grid (111,4) = 444 CTAs, 256 thr, 3 CTAs/SM (71.8 KB smem).
//   - STAGE: warp w preprocesses group gs+w: match/rank/mx/popc ONCE,
//     packed word  label | rank<<10 | mx<<15 | popc<<20  -> slab.
//   - CONSUME: warp w owns 4 channels = ONE float4 row acc4[w][513]
//     (w<4: pred ch 4w..4w+3, w>=4: targ). Per j-step: 1 LDS.128 + 4 FADD +
//     1 STS.128 (was 2x LDS.64 + 2x STS.64 -> ~40% fewer smem wavefronts).
//     Dup labels serialized by rank rounds (mx warp-uniform, converged loop).
//   - label 0 accumulates into never-read slot 0.
//   - merge via red.global.add.v4 into __device__ scratch; last CTA
//     finalizes into d_out and re-zeros scratch (deterministic replays).

#define FULLMASK 0xffffffffu

constexpr int C       = 16;
constexpr int HW      = 1 << 20;
constexpr int NLAB    = 512;
constexpr int STRIPS  = 111;             // 444 CTAs = 3/SM
constexpr int NG      = HW / 128;        // 8192 groups of 128 px per image
constexpr int R4      = 513;             // float4 slots per row
constexpr int ROWF    = 4 * R4;          // 2052 floats per row
constexpr int ACC_F   = 8 * ROWF + 513;  // 8 float4 rows + cnt = 16929
constexpr int ACC_PAD = (ACC_F + 3) & ~3;        // 16932, slab 16B-aligned
constexpr int STAGE_G = 8;               // one group per warp
constexpr int LAB_I   = STAGE_G * 128;   // 1024 packed words
constexpr int SMEM_F  = ACC_PAD + LAB_I; // 17956 floats = 71824 B

__device__ __align__(16) float g_acc[67584];
__device__ unsigned g_done = 0;

__device__ __forceinline__ void red4(float* p, float a, float b, float c, float d) {
    asm volatile("red.global.add.v4.f32 [%0], {%1,%2,%3,%4};"
                 :: "l"(p), "f"(a), "f"(b), "f"(c), "f"(d) : "memory");
}

__global__ __launch_bounds__(256, 3)
void fused_kernel(const float* __restrict__ pred,
                  const float* __restrict__ targ,
                  const int*   __restrict__ nuc,
                  float* __restrict__ out, int nCTA)
{
    extern __shared__ float sm[];
    float* cnt  = sm + 8 * ROWF;
    int*   slab = (int*)(sm + ACC_PAD);
    __shared__ int lastFlag;

    const int tid  = threadIdx.x;
    const int warp = tid >> 5;
    const int lane = tid & 31;
    const int b    = blockIdx.y;
    const int s    = blockIdx.x;

    // ---- zero accumulators ----
    {
        float4 z = make_float4(0.f, 0.f, 0.f, 0.f);
        float4* p4 = reinterpret_cast<float4*>(sm);
        for (int i = tid; i < (ACC_PAD >> 2); i += 256) p4[i] = z;
    }

    const float* planeBase = ((warp >= 4) ? targ : pred)
                             + (size_t)(b * C + (warp & 3) * 4) * HW;
    const int* lab = nuc + (size_t)b * HW;
    float4* row4 = reinterpret_cast<float4*>(sm) + warp * R4;
    const bool doCnt = (warp == 0);

    const int g0 = (s * NG) / STRIPS;
    const int g1 = ((s + 1) * NG) / STRIPS;

    for (int gs = g0; gs < g1; gs += STAGE_G) {
        const int ge = min(gs + STAGE_G, g1);
        __syncthreads();   // WAR on slab (and first-iter acc-zero ordering)

        // ---- STAGE: warp w preprocesses group gs+w (match ONCE) ----
        if (warp < ge - gs) {
            const int g = gs + warp;
            int4 L = __ldg((const int4*)(lab + (g << 7) + (lane << 2)));
            int lv[4] = {L.x, L.y, L.z, L.w};
            #pragma unroll
            for (int j = 0; j < 4; ++j) {
                const int label = lv[j];
                const unsigned grp  = __match_any_sync(FULLMASK, label);
                const int      rank = __popc(grp & ((1u << lane) - 1u));
                const int      mx   = __reduce_max_sync(FULLMASK, rank);
                const int      pc   = __popc(grp);
                lv[j] = label | (rank << 10) | (mx << 15) | (pc << 20);
            }
            *(int4*)(slab + (warp << 7) + (lane << 2)) =
                make_int4(lv[0], lv[1], lv[2], lv[3]);
        }
        __syncthreads();

        // ---- CONSUME: all warps, no warp-collectives, 1x float4 RMW ----
        for (int g = gs; g < ge; ++g) {
            const int baseG = (g << 7) + (lane << 2);
            float4 V0 = __ldg((const float4*)(planeBase + baseG));
            float4 V1 = __ldg((const float4*)(planeBase + HW + baseG));
            float4 V2 = __ldg((const float4*)(planeBase + 2 * (size_t)HW + baseG));
            float4 V3 = __ldg((const float4*)(planeBase + 3 * (size_t)HW + baseG));
            int4 P = *(const int4*)(slab + ((g - gs) << 7) + (lane << 2));

            const int   pv[4] = {P.x, P.y, P.z, P.w};
            const float c0[4] = {V0.x, V0.y, V0.z, V0.w};
            const float c1[4] = {V1.x, V1.y, V1.z, V1.w};
            const float c2[4] = {V2.x, V2.y, V2.z, V2.w};
            const float c3[4] = {V3.x, V3.y, V3.z, V3.w};

            #pragma unroll
            for (int j = 0; j < 4; ++j) {
                const int p     = pv[j];
                const int label = p & 1023;
                const int rank  = (p >> 10) & 31;
                const int mx    = (p >> 15) & 31;   // warp-uniform

                if (rank == 0) {
                    float4 x = row4[label];
                    x.x += c0[j]; x.y += c1[j]; x.z += c2[j]; x.w += c3[j];
                    row4[label] = x;
                    if (doCnt) cnt[label] += (float)((p >> 20) & 63);
                }
                for (int r = 1; r <= mx; ++r) {      // rare (mx>=1 ~62%)
                    if (rank == r) {
                        float4 x = row4[label];
                        x.x += c0[j]; x.y += c1[j]; x.z += c2[j]; x.w += c3[j];
                        row4[label] = x;
                    }
                }
            }
        }
    }
    __syncthreads();

    // ---- merge partials into global scratch ----
    for (int r = tid; r < NLAB; r += 256) {
        const int   L = r + 1;
        const float c = cnt[L];
        if (c != 0.f) {
            const int gi = b * NLAB + r;
            float* po = g_acc + (size_t)gi * C;
            float* to = g_acc + 32768 + (size_t)gi * C;
            #pragma unroll
            for (int k = 0; k < 16; k += 4) {  // pred channels k..k+3 -> row k/4
                const float* src = sm + (k >> 2) * ROWF + 4 * L;
                red4(po + k, src[0], src[1], src[2], src[3]);
            }
            #pragma unroll
            for (int k = 0; k < 16; k += 4) {  // targ channels -> row 4+k/4
                const float* src = sm + (4 + (k >> 2)) * ROWF + 4 * L;
                red4(to + k, src[0], src[1], src[2], src[3]);
            }
            atomicAdd(g_acc + 65536 + gi, c);
        }
    }
    __threadfence();
    __syncthreads();
    if (tid == 0) lastFlag = (atomicAdd(&g_done, 1u) == (unsigned)(nCTA - 1));
    __syncthreads();

    // ---- last CTA: finalize into d_out, re-zero scratch ----
    if (lastFlag) {
        __threadfence();
        const float4 z = make_float4(0.f, 0.f, 0.f, 0.f);
        for (int i = tid; i < 4 * NLAB; i += 256) {
            const float c = g_acc[65536 + i];
            const float inv = 1.0f / fmaxf(c, 1.0f);
            float4* gp = reinterpret_cast<float4*>(g_acc + (size_t)i * C);
            float4* gt = reinterpret_cast<float4*>(g_acc + 32768 + (size_t)i * C);
            float4* op = reinterpret_cast<float4*>(out + (size_t)i * C);
            float4* ot = reinterpret_cast<float4*>(out + 32768 + (size_t)i * C);
            #pragma unroll
            for (int q = 0; q < 4; ++q) {
                float4 vp = gp[q], vt = gt[q];
                vp.x *= inv; vp.y *= inv; vp.z *= inv; vp.w *= inv;
                vt.x *= inv; vt.y *= inv; vt.z *= inv; vt.w *= inv;
                op[q] = vp; ot[q] = vt;
                gp[q] = z;  gt[q] = z;
            }
            out[65536 + i]   = (c > 0.f) ? (float)((i & (NLAB - 1)) + 1) : 0.f;
            g_acc[65536 + i] = 0.f;
        }
        __syncthreads();
        if (tid == 0) g_done = 0u;
    }
}

extern "C" void kernel_launch(void* const* d_in, const int* in_sizes, int n_in,
                              void* d_out, int out_size)
{
    const float* pred = (const float*)d_in[0];
    const float* targ = (const float*)d_in[1];
    const int*   nuc  = (const int*)d_in[2];
    float* out = (float*)d_out;

    const int B = in_sizes[2] / HW;   // 4

    const int smemB = SMEM_F * (int)sizeof(float);
    cudaFuncSetAttribute(fused_kernel,
                         cudaFuncAttributeMaxDynamicSharedMemorySize, smemB);

    dim3 grid(STRIPS, B);
    fused_kernel<<<grid, 256, smemB>>>(pred, targ, nuc, out, STRIPS * B);
}